// round 1
// baseline (speedup 1.0000x reference)
#include <cuda_runtime.h>
#include <cstdint>

// Problem constants (fixed-shape problem)
#define BB 4
#define TT 12
#define NN 10000
#define FF 32
#define EE 160000
#define MM (BB*NN)          // 40000 node-batch rows
#define SLICES (BB*TT)      // 48
#define SL (NN*FF)          // elements per (b,t) slice = 320000

// -------- device scratch (static, no allocation) --------
__device__ float d_XA[SLICES * NN * FF];   // aggregated features, all slices (61.4MB)
__device__ float d_H[MM * FF];             // GRU hidden state
__device__ float d_Hacc[MM * FF];          // attention-weighted accumulator
__device__ float d_deg[NN];
__device__ float d_dinv[NN];
__device__ int   d_cnt[NN];
__device__ int   d_fill[NN];
__device__ int   d_rowptr[NN + 1];
__device__ int   d_csr_row[EE];
__device__ float d_csr_w[EE];
__device__ float d_Wf[3 * 1024];           // folded W'_z, W'_r, W'_h (32x32 each)
__device__ float d_bf[3 * 32];             // folded biases
__device__ float d_probs[TT];              // softmax(attention)

// -------- prep: fold weights, softmax attention --------
__global__ void k_prep(const float* att,
                       const float* Wz, const float* bz, const float* lzw, const float* lzb,
                       const float* Wr, const float* br, const float* lrw, const float* lrb,
                       const float* Wh, const float* bh, const float* lhw, const float* lhb) {
    int tid = threadIdx.x;                 // 1024 threads
    const float* Ws[3]  = {Wz, Wr, Wh};
    const float* bs[3]  = {bz, br, bh};
    const float* ls[3]  = {lzw, lrw, lhw};
    const float* lbs[3] = {lzb, lrb, lhb};
    int k = tid >> 5, j = tid & 31;        // k,j in [0,32)
    #pragma unroll
    for (int g = 0; g < 3; g++) {
        float s = 0.f;
        #pragma unroll
        for (int m = 0; m < 32; m++) s += Ws[g][k * 32 + m] * ls[g][m * 32 + j];
        d_Wf[g * 1024 + k * 32 + j] = s;
    }
    if (tid < 96) {
        int g = tid >> 5; int jj = tid & 31;
        float s = lbs[g][jj];
        for (int m = 0; m < 32; m++) s += bs[g][m] * ls[g][m * 32 + jj];
        d_bf[g * 32 + jj] = s;
    }
    if (tid == 0) {
        float mx = -1e30f;
        for (int i = 0; i < TT; i++) mx = fmaxf(mx, att[i]);
        float e[TT]; float sum = 0.f;
        for (int i = 0; i < TT; i++) { e[i] = expf(att[i] - mx); sum += e[i]; }
        for (int i = 0; i < TT; i++) d_probs[i] = e[i] / sum;
    }
}

// -------- CSR build --------
__global__ void k_zero() {
    int i = blockIdx.x * blockDim.x + threadIdx.x;
    if (i < NN) { d_deg[i] = 0.f; d_cnt[i] = 0; d_fill[i] = 0; }
}

__global__ void k_degcnt(const int* ei, const float* ew) {
    int e = blockIdx.x * blockDim.x + threadIdx.x;
    if (e >= EE) return;
    int col = ei[EE + e];
    atomicAdd(&d_deg[col], ew[e]);
    atomicAdd(&d_cnt[col], 1);
}

__global__ void k_dinv() {
    int n = blockIdx.x * blockDim.x + threadIdx.x;
    if (n >= NN) return;
    float d = d_deg[n] + 1.0f;             // + self loop weight 1.0
    d_dinv[n] = (d > 0.f) ? rsqrtf(fmaxf(d, 1e-12f)) : 0.f;
}

// single-block exclusive scan over d_cnt -> d_rowptr (10000 elements, 10 chunks)
__global__ void k_scan() {
    __shared__ int sh[1024];
    __shared__ int carry;
    if (threadIdx.x == 0) carry = 0;
    __syncthreads();
    for (int base = 0; base < NN; base += 1024) {
        int i = base + threadIdx.x;
        int v = (i < NN) ? d_cnt[i] : 0;
        sh[threadIdx.x] = v;
        __syncthreads();
        for (int off = 1; off < 1024; off <<= 1) {
            int t = (threadIdx.x >= off) ? sh[threadIdx.x - off] : 0;
            __syncthreads();
            sh[threadIdx.x] += t;
            __syncthreads();
        }
        if (i < NN) d_rowptr[i] = carry + sh[threadIdx.x] - v;  // exclusive
        __syncthreads();
        if (threadIdx.x == 0) carry += sh[1023];
        __syncthreads();
    }
    if (threadIdx.x == 0) d_rowptr[NN] = carry;
}

__global__ void k_fill(const int* ei, const float* ew) {
    int e = blockIdx.x * blockDim.x + threadIdx.x;
    if (e >= EE) return;
    int r = ei[e];
    int c = ei[EE + e];
    int pos = d_rowptr[c] + atomicAdd(&d_fill[c], 1);
    d_csr_row[pos] = r;
    d_csr_w[pos] = d_dinv[r] * ew[e] * d_dinv[c];
}

// -------- aggregation: XA[s,n,:] = sum_e norm_e * x[s,row_e,:] + selfw_n * x[s,n,:]
// one warp per (node, group of 8 slices); lane = feature
__global__ void k_agg(const float* __restrict__ x) {
    int w = (blockIdx.x * blockDim.x + threadIdx.x) >> 5;
    int lane = threadIdx.x & 31;
    if (w >= NN * 6) return;
    int n = w / 6, g = w % 6;
    float dn = d_dinv[n];
    float selfw = dn * dn;
    int nb = n * 32 + lane;
    float acc[8];
    #pragma unroll
    for (int u = 0; u < 8; u++)
        acc[u] = selfw * __ldg(&x[(g * 8 + u) * SL + nb]);
    int e0 = d_rowptr[n], e1 = d_rowptr[n + 1];
    for (int e = e0; e < e1; e++) {
        int r = d_csr_row[e];
        float wgt = d_csr_w[e];
        int rb = r * 32 + lane;
        #pragma unroll
        for (int u = 0; u < 8; u++)
            acc[u] += wgt * __ldg(&x[(g * 8 + u) * SL + rb]);
    }
    #pragma unroll
    for (int u = 0; u < 8; u++)
        d_XA[(g * 8 + u) * SL + nb] = acc[u];
}

// -------- fused GRU step (one launch per t), one warp per 4 (b,n) rows --------
__global__ void k_step(int t,
                       const float* __restrict__ lzw,
                       const float* __restrict__ lrw,
                       const float* __restrict__ lhw) {
    __shared__ float sWz[1024], sWr[1024], sWh[1024];
    __shared__ float sUz[1024], sUr[1024], sUh[1024];
    __shared__ float sb[96];
    __shared__ float sprob;
    for (int i = threadIdx.x; i < 1024; i += blockDim.x) {
        sWz[i] = d_Wf[i];
        sWr[i] = d_Wf[1024 + i];
        sWh[i] = d_Wf[2048 + i];
        sUz[i] = lzw[1024 + i];   // bottom half of [64,32] weight
        sUr[i] = lrw[1024 + i];
        sUh[i] = lhw[1024 + i];
    }
    if (threadIdx.x < 96) sb[threadIdx.x] = d_bf[threadIdx.x];
    if (threadIdx.x == 0) sprob = d_probs[t];
    __syncthreads();

    int w = (blockIdx.x * blockDim.x + threadIdx.x) >> 5;
    int lane = threadIdx.x & 31;
    if (w >= MM / 4) return;
    int m0 = w * 4;

    float bz = sb[lane], br = sb[32 + lane], bh = sb[64 + lane];
    float xa[4], h[4], az[4], ar[4], ah[4];
    #pragma unroll
    for (int u = 0; u < 4; u++) {
        int m = m0 + u;
        int b = m / NN;
        int n = m - b * NN;
        xa[u] = d_XA[((b * TT + t) * NN + n) * 32 + lane];
        h[u] = (t == 0) ? 0.f : d_H[m * 32 + lane];
        az[u] = bz; ar[u] = br; ah[u] = bh;
    }
    #pragma unroll
    for (int k = 0; k < 32; k++) {
        float wz = sWz[k * 32 + lane], wr = sWr[k * 32 + lane], wh = sWh[k * 32 + lane];
        float uz = sUz[k * 32 + lane], ur = sUr[k * 32 + lane];
        #pragma unroll
        for (int u = 0; u < 4; u++) {
            float xk = __shfl_sync(0xffffffffu, xa[u], k);
            float hk = __shfl_sync(0xffffffffu, h[u], k);
            az[u] += xk * wz + hk * uz;
            ar[u] += xk * wr + hk * ur;
            ah[u] += xk * wh;
        }
    }
    float z[4], hr[4];
    #pragma unroll
    for (int u = 0; u < 4; u++) {
        z[u] = 1.f / (1.f + __expf(-az[u]));
        float R = 1.f / (1.f + __expf(-ar[u]));
        hr[u] = h[u] * R;
    }
    #pragma unroll
    for (int k = 0; k < 32; k++) {
        float uh = sUh[k * 32 + lane];
        #pragma unroll
        for (int u = 0; u < 4; u++)
            ah[u] += __shfl_sync(0xffffffffu, hr[u], k) * uh;
    }
    #pragma unroll
    for (int u = 0; u < 4; u++) {
        float Ht = tanhf(ah[u]);
        float Hn = z[u] * h[u] + (1.f - z[u]) * Ht;
        int m = m0 + u;
        d_H[m * 32 + lane] = Hn;
        if (t == 0) d_Hacc[m * 32 + lane] = sprob * Hn;
        else        d_Hacc[m * 32 + lane] += sprob * Hn;
    }
}

// -------- final: out = relu(Hacc) @ lin_w + lin_b --------
__global__ void k_final(const float* __restrict__ linw,
                        const float* __restrict__ linb,
                        float* __restrict__ out) {
    __shared__ float sW[1024];
    __shared__ float sb2[32];
    for (int i = threadIdx.x; i < 1024; i += blockDim.x) sW[i] = linw[i];
    if (threadIdx.x < 32) sb2[threadIdx.x] = linb[threadIdx.x];
    __syncthreads();

    int w = (blockIdx.x * blockDim.x + threadIdx.x) >> 5;
    int lane = threadIdx.x & 31;
    if (w >= MM / 4) return;
    int m0 = w * 4;
    float v[4], acc[4];
    #pragma unroll
    for (int u = 0; u < 4; u++) {
        v[u] = fmaxf(d_Hacc[(m0 + u) * 32 + lane], 0.f);
        acc[u] = sb2[lane];
    }
    #pragma unroll
    for (int k = 0; k < 32; k++) {
        float lw = sW[k * 32 + lane];
        #pragma unroll
        for (int u = 0; u < 4; u++)
            acc[u] += __shfl_sync(0xffffffffu, v[u], k) * lw;
    }
    #pragma unroll
    for (int u = 0; u < 4; u++)
        out[(m0 + u) * 32 + lane] = acc[u];
}

extern "C" void kernel_launch(void* const* d_in, const int* in_sizes, int n_in,
                              void* d_out, int out_size) {
    const float* x  = (const float*)d_in[0];
    const int*   ei = (const int*)d_in[1];
    const float* ew = (const float*)d_in[2];

    // Detect weight ordering at runtime:
    //  dict order:      W_z,b_z,lz_w,lz_b, W_r,b_r,lr_w,lr_b, W_h,b_h,lh_w,lh_b  -> in_sizes[5]==2048
    //  signature order: W_z,b_z,W_r,b_r,W_h,b_h, lz_w,lz_b,lr_w,lr_b,lh_w,lh_b  -> in_sizes[5]==1024
    int iWz, iBz, iLzw, iLzb, iWr, iBr, iLrw, iLrb, iWh, iBh, iLhw, iLhb;
    if (in_sizes[5] == 2048) {
        iWz = 3; iBz = 4; iLzw = 5;  iLzb = 6;
        iWr = 7; iBr = 8; iLrw = 9;  iLrb = 10;
        iWh = 11; iBh = 12; iLhw = 13; iLhb = 14;
    } else {
        iWz = 3; iBz = 4; iWr = 5; iBr = 6; iWh = 7; iBh = 8;
        iLzw = 9; iLzb = 10; iLrw = 11; iLrb = 12; iLhw = 13; iLhb = 14;
    }
    const float* Wz  = (const float*)d_in[iWz];
    const float* bz  = (const float*)d_in[iBz];
    const float* lzw = (const float*)d_in[iLzw];
    const float* lzb = (const float*)d_in[iLzb];
    const float* Wr  = (const float*)d_in[iWr];
    const float* br  = (const float*)d_in[iBr];
    const float* lrw = (const float*)d_in[iLrw];
    const float* lrb = (const float*)d_in[iLrb];
    const float* Wh  = (const float*)d_in[iWh];
    const float* bh  = (const float*)d_in[iBh];
    const float* lhw = (const float*)d_in[iLhw];
    const float* lhb = (const float*)d_in[iLhb];
    const float* att  = (const float*)d_in[15];
    const float* linw = (const float*)d_in[16];
    const float* linb = (const float*)d_in[17];
    float* out = (float*)d_out;

    // CSR build + prep
    k_zero<<<(NN + 255) / 256, 256>>>();
    k_prep<<<1, 1024>>>(att, Wz, bz, lzw, lzb, Wr, br, lrw, lrb, Wh, bh, lhw, lhb);
    k_degcnt<<<(EE + 255) / 256, 256>>>(ei, ew);
    k_dinv<<<(NN + 255) / 256, 256>>>();
    k_scan<<<1, 1024>>>();
    k_fill<<<(EE + 255) / 256, 256>>>(ei, ew);

    // aggregation for all 48 (b,t) slices: 60000 warps
    {
        int warps = NN * 6;
        int threads = warps * 32;
        k_agg<<<(threads + 255) / 256, 256>>>(x);
    }

    // GRU recurrence, sequential over T
    {
        int warps = MM / 4;                 // 10000
        int blk = 1024;                     // 32 warps/block
        int grid = (warps * 32 + blk - 1) / blk;
        for (int t = 0; t < TT; t++)
            k_step<<<grid, blk>>>(t, lzw, lrw, lhw);
    }

    // final projection
    {
        int warps = MM / 4;
        int blk = 256;
        int grid = (warps * 32 + blk - 1) / blk;
        k_final<<<grid, blk>>>(linw, linb, out);
    }
    (void)n_in; (void)out_size;
}